// round 8
// baseline (speedup 1.0000x reference)
#include <cuda_runtime.h>

// LSTM B=1024 T=512 F=40 H=50 + MLP head. Round 6: one barrier per step.
//
// 256 CTAs x 256 threads, RR=4 rows/CTA, 2 CTAs/SM (<=128 regs).
// Thread map (compute, tid<224): u = tid/4, g = tid%4 -> gate row j = g*50+u.
//   Each holds full combined W row (padded 92) as 46 packed f32x2 regs and
//   computes gate g of unit u for all 4 batch rows (fma.rn.f32x2 vs broadcast
//   ld.shared.v2.u64 of z). Gates exchanged inside the lane QUAD via shfl;
//   lane g performs the cell update for row r=g (register c-state) and stores
//   its h. z = [x_t | h] is double-buffered -> ONE __syncthreads per step.
// Warp 7 (tid 224..255): x prefetch, 40 float4 slots, 2 steps ahead.

#define TT   512
#define FF   40
#define HH   50
#define GG   200
#define RR   4
#define KP   92           // padded combined K (40 x | 50 h | 2 pad) = 23 f4
#define NC   200          // real compute threads (tid<224 incl. 24 dummies)
#define NTH  256
#define NGRID 256         // 1024 / RR

__device__ __forceinline__ unsigned long long pk2(float lo, float hi) {
    unsigned long long r;
    asm("mov.b64 %0, {%1, %2};" : "=l"(r) : "f"(lo), "f"(hi));
    return r;
}
__device__ __forceinline__ void upk2(unsigned long long v, float& lo, float& hi) {
    asm("mov.b64 {%0, %1}, %2;" : "=f"(lo), "=f"(hi) : "l"(v));
}
__device__ __forceinline__ unsigned long long f2fma(unsigned long long a,
                                                   unsigned long long b,
                                                   unsigned long long c) {
    unsigned long long d;
    asm("fma.rn.f32x2 %0, %1, %2, %3;" : "=l"(d) : "l"(a), "l"(b), "l"(c));
    return d;
}
__device__ __forceinline__ float tanh_f(float x) {
    float y;
    asm("tanh.approx.f32 %0, %1;" : "=f"(y) : "f"(x));
    return y;
}
__device__ __forceinline__ float sig_f(float x) {
    return fmaf(0.5f, tanh_f(0.5f * x), 0.5f);
}
__device__ __forceinline__ float wfetch(const float* __restrict__ Wih,
                                        const float* __restrict__ Whh,
                                        int j, int k) {
    if (k < FF)       return Wih[j * FF + k];
    if (k < FF + HH)  return Whh[j * HH + (k - FF)];
    return 0.0f;
}

__global__ __launch_bounds__(NTH, 2)
void lstm_kernel(const float* __restrict__ x,   const float* __restrict__ Wih,
                 const float* __restrict__ Whh, const float* __restrict__ bih,
                 const float* __restrict__ bhh, const float* __restrict__ W1,
                 const float* __restrict__ b1,  const float* __restrict__ W2,
                 const float* __restrict__ b2,  float* __restrict__ out)
{
    __shared__ __align__(16) float sZ[2][RR][KP];   // double-buffered z
    __shared__ __align__(16) float sH[RR * 10];     // head scratch

    const int tid  = threadIdx.x;
    const int b0   = blockIdx.x * RR;
    const int lane = tid & 31;

    // ---- zero both z buffers ----
    for (int i = tid; i < 2 * RR * KP; i += NTH) ((float*)sZ)[i] = 0.0f;

    // ---- compute roles: u = tid/4, g = tid%4, gate row j = g*50+u ----
    const int u = tid >> 2;
    const int g = tid & 3;
    const int j = g * HH + u;                 // valid when u < HH
    const bool real = (u < HH);               // tids 200..223 are dummies

    unsigned long long w[46];
    #pragma unroll
    for (int kk = 0; kk < 46; ++kk) {
        float lo = (tid < NC) ? wfetch(Wih, Whh, j, 2 * kk)     : 0.0f;
        float hi = (tid < NC) ? wfetch(Wih, Whh, j, 2 * kk + 1) : 0.0f;
        w[kk] = pk2(lo, hi);
    }
    const unsigned long long bias0 =
        (tid < NC) ? pk2(bih[j] + bhh[j], 0.0f) : 0ull;

    // shfl source lanes within the quad
    const int ql = lane & ~3;

    // c-state for (row g, unit u): c0[:,0] = 1
    float creg = (u == 0) ? 1.0f : 0.0f;

    // ---- loader roles: warp 7, lane l owns slot l (and l+32 if l<8) ----
    const int l   = tid - 224;
    const int rA  = (l >= 0) ? (l / 10) : 0;
    const int qA  = (l >= 0) ? (l - rA * 10) : 0;
    const int lB  = l + 32;                       // second slot for l<8
    const int rB  = lB / 10, qB = lB - rB * 10;
    const bool hasB = (l >= 0 && l < 8);
    const float4* __restrict__ xv = (const float4*)x;
    float4 xnA = make_float4(0.f,0.f,0.f,0.f), xnB = xnA;

    __syncthreads();
    if (tid >= 224) {                             // x_0 -> buf0 ; prefetch x_1
        ((float4*)&sZ[0][rA][0])[qA] = xv[((b0 + rA) * TT + 0) * 10 + qA];
        xnA = xv[((b0 + rA) * TT + 1) * 10 + qA];
        if (hasB) {
            ((float4*)&sZ[0][rB][0])[qB] = xv[((b0 + rB) * TT + 0) * 10 + qB];
            xnB = xv[((b0 + rB) * TT + 1) * 10 + qB];
        }
    }
    __syncthreads();

    // ================= recurrence: ONE barrier per step =================
    #pragma unroll 2
    for (int t = 0; t < TT; ++t) {
        const int p = t & 1;
        const float* __restrict__ zr = &sZ[p][0][0];
        float* __restrict__       zw = &sZ[1 - p][0][0];

        if (tid < 224) {
            // gemv: gate (g,u) for rows 0..3, full K, register weights
            unsigned long long a0 = bias0, a1 = bias0, a2 = bias0, a3 = bias0;
            const ulonglong2* __restrict__ zb = (const ulonglong2*)zr;
            #pragma unroll
            for (int i = 0; i < 23; ++i) {
                ulonglong2 z0 = zb[ 0 + i];
                ulonglong2 z1 = zb[23 + i];
                ulonglong2 z2 = zb[46 + i];
                ulonglong2 z3 = zb[69 + i];
                unsigned long long wa = w[2 * i], wb = w[2 * i + 1];
                a0 = f2fma(wa, z0.x, a0); a0 = f2fma(wb, z0.y, a0);
                a1 = f2fma(wa, z1.x, a1); a1 = f2fma(wb, z1.y, a1);
                a2 = f2fma(wa, z2.x, a2); a2 = f2fma(wb, z2.y, a2);
                a3 = f2fma(wa, z3.x, a3); a3 = f2fma(wb, z3.y, a3);
            }
            float af[4], lo, hi;
            upk2(a0, lo, hi); af[0] = lo + hi;
            upk2(a1, lo, hi); af[1] = lo + hi;
            upk2(a2, lo, hi); af[2] = lo + hi;
            upk2(a3, lo, hi); af[3] = lo + hi;

            // quad exchange: lane g keeps row r=g's four gates
            float Gi = 0.f, Gf = 0.f, Gc = 0.f, Go = 0.f;
            #pragma unroll
            for (int r = 0; r < 4; ++r) {
                float vi = __shfl_sync(0xffffffffu, af[r], ql | 0);
                float vf = __shfl_sync(0xffffffffu, af[r], ql | 1);
                float vc = __shfl_sync(0xffffffffu, af[r], ql | 2);
                float vo = __shfl_sync(0xffffffffu, af[r], ql | 3);
                if (r == g) { Gi = vi; Gf = vf; Gc = vc; Go = vo; }
            }

            // cell update for (row g, unit u); h -> next buffer
            float si = sig_f(Gi);
            float sf = sig_f(Gf);
            float tg = tanh_f(Gc);
            float so = sig_f(Go);
            creg = fmaf(sf, creg, si * tg);
            float h = so * tanh_f(creg);
            if (real) zw[g * KP + FF + u] = h;
        } else if ((t + 1) < TT) {
            // commit x_{t+1} into next buffer; prefetch x_{t+2}
            ((float4*)(zw + rA * KP))[qA] = xnA;
            if (hasB) ((float4*)(zw + rB * KP))[qB] = xnB;
            if ((t + 2) < TT) {
                xnA = xv[((b0 + rA) * TT + (t + 2)) * 10 + qA];
                if (hasB) xnB = xv[((b0 + rB) * TT + (t + 2)) * 10 + qB];
            }
        }
        __syncthreads();
    }

    // ================= MLP head (final h lives in buf0) =================
    if (tid < RR * 10) {
        int r = tid / 10, m = tid - (tid / 10) * 10;
        float s = b1[m];
        #pragma unroll
        for (int uu = 0; uu < HH; ++uu)
            s = fmaf(sZ[0][r][FF + uu], W1[m * HH + uu], s);
        sH[tid] = fmaxf(s, 0.0f);
    }
    __syncthreads();

    if (tid < RR) {
        float o = b2[0];
        #pragma unroll
        for (int m = 0; m < 10; ++m)
            o = fmaf(sH[tid * 10 + m], W2[m], o);
        out[b0 + tid] = o + x[((b0 + tid) * TT + (TT - 1)) * FF + 0];
    }
}

extern "C" void kernel_launch(void* const* d_in, const int* in_sizes, int n_in,
                              void* d_out, int out_size)
{
    const float* x   = (const float*)d_in[0];
    const float* Wih = (const float*)d_in[1];
    const float* Whh = (const float*)d_in[2];
    const float* bih = (const float*)d_in[3];
    const float* bhh = (const float*)d_in[4];
    const float* W1  = (const float*)d_in[5];
    const float* b1  = (const float*)d_in[6];
    const float* W2  = (const float*)d_in[7];
    const float* b2  = (const float*)d_in[8];
    float* out = (float*)d_out;

    lstm_kernel<<<NGRID, NTH>>>(x, Wih, Whh, bih, bhh, W1, b1, W2, b2, out);
}